// round 8
// baseline (speedup 1.0000x reference)
#include <cuda_runtime.h>
#include <cuda_bf16.h>
#include <stdint.h>

#define Nn    4096
#define Dd    512
#define D4    128        // Dd/4
#define NE    131072
#define WPR   128
#define SLOTS 128
#define UPBLK 128        // blocks in fused u-kernel (must be <= #SMs for residency)

// ---------------- scratch ----------------
__device__ uint32_t g_bm [Nn * WPR];
__device__ uint32_t g_bmT[Nn * WPR];
__device__ int      g_cols [Nn * SLOTS];
__device__ int      g_colsT[Nn * SLOTS];
__device__ int      g_cnt [Nn];
__device__ int      g_cntT[Nn];
__device__ float    g_dinv[Nn];
__device__ float    g_v[Nn];
__device__ float    g_u[Nn], g_u2[Nn];
__device__ float    g_q[Dd];             // raw u^T X sums (atomicAdd from Rpass)
__device__ float    g_qs;                // 0.6^4 * 1.5 / (u.v)
__device__ float    g_Af[Nn * Dd];       // R fp32 (final-pass base)
__device__ uint2    g_Ab[Nn * D4];       // R bf16 (middle-pass base + iterate0)
__device__ uint2    g_Xb[Nn * D4];       // X bf16 (R-pass gathers)
__device__ uint2    g_bf0[Nn * D4];      // iterate ping
__device__ uint2    g_bf1[Nn * D4];      // iterate pong
__device__ int      g_is64;
__device__ int      g_bar[8];            // grid-barrier counters (re-zeroed per call)

// ---------------- helpers ----------------
__device__ __forceinline__ float4 bf2f4(uint2 r) {
    float2 a = __bfloat1622float2(*(__nv_bfloat162*)&r.x);
    float2 b = __bfloat1622float2(*(__nv_bfloat162*)&r.y);
    return make_float4(a.x, a.y, b.x, b.y);
}
__device__ __forceinline__ uint2 f42bf(float4 x) {
    __nv_bfloat162 p0 = __float22bfloat162_rn(make_float2(x.x, x.y));
    __nv_bfloat162 p1 = __float22bfloat162_rn(make_float2(x.z, x.w));
    uint2 o; o.x = *(uint32_t*)&p0; o.y = *(uint32_t*)&p1;
    return o;
}
// software grid barrier (all blocks co-resident); volatile poll, atomic arrive
__device__ __forceinline__ void gridbar(int idx, int nb) {
    __syncthreads();
    if (threadIdx.x == 0) {
        __threadfence();
        atomicAdd(&g_bar[idx], 1);
        volatile int* p = &g_bar[idx];
        while (*p < nb) {}
    }
    __syncthreads();
}

// ---------------- init: zero bitmaps + barriers + q, u=1, sniff dtype ------------
__global__ void k_init(const int* __restrict__ ei32) {
    int gid = blockIdx.x * blockDim.x + threadIdx.x;   // 1024 x 256 = 262144
    if (gid < Nn * WPR / 4)  ((uint4*)g_bm )[gid]            = make_uint4(0,0,0,0);
    else                     ((uint4*)g_bmT)[gid - Nn*WPR/4] = make_uint4(0,0,0,0);
    if (gid < Nn)  g_u[gid] = 1.0f;
    if (gid < Dd)  g_q[gid] = 0.0f;
    if (gid < 8)   g_bar[gid] = 0;
    // sniff int64 vs int32: int64 values < 4096 have all-zero odd 32-bit words
    if (blockIdx.x == 1023 && threadIdx.x < 32) {
        int t = threadIdx.x, acc = 0;
        for (int k = t; k < 1024; k += 32) acc |= ei32[2*k + 1];
#pragma unroll
        for (int d = 16; d; d >>= 1) acc |= __shfl_xor_sync(0xFFFFFFFFu, acc, d);
        if (t == 0) g_is64 = (acc == 0);
    }
}

__global__ void k_scatter2(const int* __restrict__ ei32) {
    int e = blockIdx.x * blockDim.x + threadIdx.x;
    if (e < NE) {
        int s, d;
        if (g_is64) { s = ei32[2*e]; d = ei32[2*(NE+e)]; }
        else        { s = ei32[e];   d = ei32[NE+e]; }
        atomicOr(&g_bm [s * WPR + (d >> 5)], 1u << (d & 31));
        atomicOr(&g_bmT[d * WPR + (s >> 5)], 1u << (s & 31));
    }
}

// build fwd+transpose CSR (blocks 0..1023) and X->bf16 (blocks 1024..3071)
__global__ void k_build_x2bf(const float4* __restrict__ x) {
    if (blockIdx.x < 1024) {
        int warp = (blockIdx.x * blockDim.x + threadIdx.x) >> 5;   // 0..8191
        int lane = threadIdx.x & 31;
        int fwd = (warp < Nn);
        int row = fwd ? warp : warp - Nn;
        const uint32_t* rowbm = fwd ? &g_bm[row * WPR] : &g_bmT[row * WPR];
        int* dst  = fwd ? &g_cols[row * SLOTS] : &g_colsT[row * SLOTS];
        uint32_t w[4]; int c = 0;
#pragma unroll
        for (int k = 0; k < 4; k++) { w[k] = rowbm[lane*4 + k]; c += __popc(w[k]); }
        int incl = c;
#pragma unroll
        for (int d = 1; d < 32; d <<= 1) {
            int t = __shfl_up_sync(0xFFFFFFFFu, incl, d);
            if (lane >= d) incl += t;
        }
        int total = __shfl_sync(0xFFFFFFFFu, incl, 31);
        int off = incl - c;
#pragma unroll
        for (int k = 0; k < 4; k++) {
            uint32_t m = w[k];
            int base = (lane*4 + k) << 5;
            while (m) { int b = __ffs(m) - 1; m &= m - 1; dst[off++] = base + b; }
        }
        if (lane == 0) {
            if (fwd) {
                g_cnt[row] = total;
                float deg = (float)(total + 1);
                g_dinv[row] = rsqrtf(deg);
                g_v[row]    = sqrtf(deg);
            } else {
                g_cntT[row] = total;
            }
        }
    } else {
        int i = (blockIdx.x - 1024) * blockDim.x + threadIdx.x;   // 0..524287
        g_Xb[i] = f42bf(x[i]);
    }
}

// ---------------- u-pipeline: 3 power iters + scale --------------------------------
// grid = UPBLK blocks x 1024 threads, co-resident; final u lives in g_u2.
__global__ __launch_bounds__(1024) void k_upower() {
    int b    = blockIdx.x;
    int t    = threadIdx.x;
    int wid  = t >> 5;          // 32 warps -> 32 rows per block
    int lane = t & 31;
    int row = b * (Nn / UPBLK) + wid;

    // 3 power iterations on Ahat^T: u -> u2 -> u -> u2
#pragma unroll
    for (int it = 0; it < 3; it++) {
        const float* src = (it == 1) ? g_u2 : g_u;
        float*       dst = (it == 1) ? g_u  : g_u2;
        int cnt = g_cntT[row];
        const int* cols = &g_colsT[row * SLOTS];
        float s = 0.f;
        for (int k = lane; k < cnt; k += 32)
            s += g_dinv[cols[k]] * src[cols[k]];
#pragma unroll
        for (int d = 16; d; d >>= 1) s += __shfl_down_sync(0xFFFFFFFFu, s, d);
        if (lane == 0) {
            float di = g_dinv[row];
            dst[row] = di * (s + di * src[row]);
        }
        gridbar(it, UPBLK);
    }

    // block 0: g_qs = 0.6^4 * 1.5 / (u . v)
    if (b == 0) {
        __shared__ float sh[32];
        float s = 0.f;
        for (int i = t; i < Nn; i += 1024) s += g_u2[i] * g_v[i];
#pragma unroll
        for (int d = 16; d; d >>= 1) s += __shfl_down_sync(0xFFFFFFFFu, s, d);
        if (lane == 0) sh[wid] = s;
        __syncthreads();
        if (t < 32) {
            s = sh[t];
#pragma unroll
            for (int d = 16; d; d >>= 1) s += __shfl_down_sync(0xFFFFFFFFu, s, d);
            if (t == 0) g_qs = 0.1944f / s;     // 0.6^4 * 1.5 / (u.v)
        }
    }
}

// ---------------- R pass: R = (I + 0.5*Ahat)X ; fused q accumulation --------------
__global__ __launch_bounds__(128) void k_Rpass(
    const float4* __restrict__ xf, const uint2* __restrict__ xb,
    float4* __restrict__ outf, uint2* __restrict__ outb)
{
    int row = blockIdx.x;
    int col = threadIdx.x;
    int cnt = g_cnt[row];
    float di = g_dinv[row];
    const int* cols = &g_cols[row * SLOTS];
    long idx = (long)row * D4 + col;

    float4 xi = __ldg(&xf[idx]);

    // fused q accumulation: q[col] += u[row] * X[row,col]  (u final = g_u2)
    {
        float ur = g_u2[row];
        atomicAdd(&g_q[4*col + 0], ur * xi.x);
        atomicAdd(&g_q[4*col + 1], ur * xi.y);
        atomicAdd(&g_q[4*col + 2], ur * xi.z);
        atomicAdd(&g_q[4*col + 3], ur * xi.w);
    }

    float4 s;
    s.x = di * xi.x; s.y = di * xi.y; s.z = di * xi.z; s.w = di * xi.w;

    int k = 0;
    for (; k + 4 <= cnt; k += 4) {
        int j0 = __ldg(&cols[k]),   j1 = __ldg(&cols[k+1]);
        int j2 = __ldg(&cols[k+2]), j3 = __ldg(&cols[k+3]);
        float w0 = __ldg(&g_dinv[j0]), w1 = __ldg(&g_dinv[j1]);
        float w2 = __ldg(&g_dinv[j2]), w3 = __ldg(&g_dinv[j3]);
        float4 v0 = bf2f4(__ldg(&xb[(long)j0 * D4 + col]));
        float4 v1 = bf2f4(__ldg(&xb[(long)j1 * D4 + col]));
        float4 v2 = bf2f4(__ldg(&xb[(long)j2 * D4 + col]));
        float4 v3 = bf2f4(__ldg(&xb[(long)j3 * D4 + col]));
        s.x += w0*v0.x + w1*v1.x + w2*v2.x + w3*v3.x;
        s.y += w0*v0.y + w1*v1.y + w2*v2.y + w3*v3.y;
        s.z += w0*v0.z + w1*v1.z + w2*v2.z + w3*v3.z;
        s.w += w0*v0.w + w1*v1.w + w2*v2.w + w3*v3.w;
    }
    for (; k < cnt; k++) {
        int j = __ldg(&cols[k]);
        float w = __ldg(&g_dinv[j]);
        float4 v = bf2f4(__ldg(&xb[(long)j * D4 + col]));
        s.x += w*v.x; s.y += w*v.y; s.z += w*v.z; s.w += w*v.w;
    }
    float hd = 0.5f * di;
    float4 o;
    o.x = xi.x + hd*s.x;
    o.y = xi.y + hd*s.y;
    o.z = xi.z + hd*s.z;
    o.w = xi.w + hd*s.w;
    outf[idx] = o;
    outb[idx] = f42bf(o);
}

// ---------------- middle bulk pass (all-bf16) ----------------
// out_bf = base_bf + 0.6*dinv_i*(sum_j dinv_j*in[j] + dinv_i*in[i])
__global__ __launch_bounds__(128) void k_bulk(
    const uint2* __restrict__ inb, const uint2* __restrict__ baseb,
    uint2* __restrict__ outb)
{
    int row = blockIdx.x;
    int col = threadIdx.x;
    int cnt = g_cnt[row];
    float di = g_dinv[row];
    const int* cols = &g_cols[row * SLOTS];
    long idx = (long)row * D4 + col;

    float4 sv = bf2f4(__ldg(&inb[idx]));
    float4 s;
    s.x = di * sv.x; s.y = di * sv.y; s.z = di * sv.z; s.w = di * sv.w;

    int k = 0;
    for (; k + 4 <= cnt; k += 4) {
        int j0 = __ldg(&cols[k]),   j1 = __ldg(&cols[k+1]);
        int j2 = __ldg(&cols[k+2]), j3 = __ldg(&cols[k+3]);
        float w0 = __ldg(&g_dinv[j0]), w1 = __ldg(&g_dinv[j1]);
        float w2 = __ldg(&g_dinv[j2]), w3 = __ldg(&g_dinv[j3]);
        float4 v0 = bf2f4(__ldg(&inb[(long)j0 * D4 + col]));
        float4 v1 = bf2f4(__ldg(&inb[(long)j1 * D4 + col]));
        float4 v2 = bf2f4(__ldg(&inb[(long)j2 * D4 + col]));
        float4 v3 = bf2f4(__ldg(&inb[(long)j3 * D4 + col]));
        s.x += w0*v0.x + w1*v1.x + w2*v2.x + w3*v3.x;
        s.y += w0*v0.y + w1*v1.y + w2*v2.y + w3*v3.y;
        s.z += w0*v0.z + w1*v1.z + w2*v2.z + w3*v3.z;
        s.w += w0*v0.w + w1*v1.w + w2*v2.w + w3*v3.w;
    }
    for (; k < cnt; k++) {
        int j = __ldg(&cols[k]);
        float w = __ldg(&g_dinv[j]);
        float4 v = bf2f4(__ldg(&inb[(long)j * D4 + col]));
        s.x += w*v.x; s.y += w*v.y; s.z += w*v.z; s.w += w*v.w;
    }
    float4 bs = bf2f4(__ldg(&baseb[idx]));
    float bd = 0.6f * di;
    float4 o;
    o.x = bs.x + bd*s.x; o.y = bs.y + bd*s.y;
    o.z = bs.z + bd*s.z; o.w = bs.w + bd*s.w;
    outb[idx] = f42bf(o);
}

// ---------------- final: Y = 0.4*R + 0.24*Ahat*acc + 0.6^4*v*q ----------------
__global__ __launch_bounds__(128) void k_final(
    const uint2* __restrict__ inb, const float4* __restrict__ basef,
    float4* __restrict__ out)
{
    int row = blockIdx.x;
    int col = threadIdx.x;
    int cnt = g_cnt[row];
    float di = g_dinv[row];
    const int* cols = &g_cols[row * SLOTS];
    long idx = (long)row * D4 + col;

    float4 sv = bf2f4(__ldg(&inb[idx]));
    float4 s;
    s.x = di * sv.x; s.y = di * sv.y; s.z = di * sv.z; s.w = di * sv.w;

    int k = 0;
    for (; k + 4 <= cnt; k += 4) {
        int j0 = __ldg(&cols[k]),   j1 = __ldg(&cols[k+1]);
        int j2 = __ldg(&cols[k+2]), j3 = __ldg(&cols[k+3]);
        float w0 = __ldg(&g_dinv[j0]), w1 = __ldg(&g_dinv[j1]);
        float w2 = __ldg(&g_dinv[j2]), w3 = __ldg(&g_dinv[j3]);
        float4 v0 = bf2f4(__ldg(&inb[(long)j0 * D4 + col]));
        float4 v1 = bf2f4(__ldg(&inb[(long)j1 * D4 + col]));
        float4 v2 = bf2f4(__ldg(&inb[(long)j2 * D4 + col]));
        float4 v3 = bf2f4(__ldg(&inb[(long)j3 * D4 + col]));
        s.x += w0*v0.x + w1*v1.x + w2*v2.x + w3*v3.x;
        s.y += w0*v0.y + w1*v1.y + w2*v2.y + w3*v3.y;
        s.z += w0*v0.z + w1*v1.z + w2*v2.z + w3*v3.z;
        s.w += w0*v0.w + w1*v1.w + w2*v2.w + w3*v3.w;
    }
    for (; k < cnt; k++) {
        int j = __ldg(&cols[k]);
        float w = __ldg(&g_dinv[j]);
        float4 v = bf2f4(__ldg(&inb[(long)j * D4 + col]));
        s.x += w*v.x; s.y += w*v.y; s.z += w*v.z; s.w += w*v.w;
    }
    float4 bs = __ldg(&basef[idx]);
    float bd = 0.24f * di;
    float rv = g_v[row] * g_qs;          // 0.6^4 * 1.5/(u.v) * v_i
    float4 q = ((const float4*)g_q)[col];
    float4 o;
    o.x = 0.4f*bs.x + bd*s.x + rv*q.x;
    o.y = 0.4f*bs.y + bd*s.y + rv*q.y;
    o.z = 0.4f*bs.z + bd*s.z + rv*q.z;
    o.w = 0.4f*bs.w + bd*s.w + rv*q.w;
    out[idx] = o;
}

// ---------------- launch ----------------
extern "C" void kernel_launch(void* const* d_in, const int* in_sizes, int n_in,
                              void* d_out, int out_size) {
    const float* x    = (const float*)d_in[0];
    const void*  eraw = d_in[1];
    if (in_sizes[0] != Nn * Dd) { x = (const float*)d_in[1]; eraw = d_in[0]; }
    const int* ei32 = (const int*)eraw;
    float4*    yo   = (float4*)d_out;

    float *pAf;  cudaGetSymbolAddress((void**)&pAf, g_Af);
    uint2 *pAb;  cudaGetSymbolAddress((void**)&pAb, g_Ab);
    uint2 *pXb;  cudaGetSymbolAddress((void**)&pXb, g_Xb);
    uint2 *pbf0; cudaGetSymbolAddress((void**)&pbf0, g_bf0);
    uint2 *pbf1; cudaGetSymbolAddress((void**)&pbf1, g_bf1);

    // 1) zero bitmaps/barriers/q, u=1, dtype sniff
    k_init<<<1024, 256>>>(ei32);
    // 2) edge scatter into dedupe bitmaps (fwd + transpose)
    k_scatter2<<<NE / 256, 256>>>(ei32);
    // 3) CSR build (fwd+T) + X->bf16
    k_build_x2bf<<<3072, 256>>>((const float4*)x);
    // 4) 3 power iterations + Perron scale
    k_upower<<<UPBLK, 1024>>>();
    // 5) R = (I + 0.5*Ahat)X  (fp32 + bf16), fused u^T X accumulation
    k_Rpass<<<Nn, 128>>>((const float4*)x, pXb, (float4*)pAf, pAb);
    // 6-7) two middle bulk passes (bf16): acc <- R + 0.6*Ahat*acc
    k_bulk<<<Nn, 128>>>(pAb,  pAb, pbf0);
    k_bulk<<<Nn, 128>>>(pbf0, pAb, pbf1);
    // 8) final: Y = 0.4*(R + 0.6*Ahat*acc) + 0.6^4*v*q
    k_final<<<Nn, 128>>>(pbf1, (const float4*)pAf, yo);
}

// round 9
// speedup vs baseline: 2.3185x; 2.3185x over previous
#include <cuda_runtime.h>
#include <cuda_bf16.h>
#include <stdint.h>

#define Nn    4096
#define Dd    512
#define D4    128        // Dd/4
#define NE    131072
#define WPR   128
#define SLOTS 128
#define UPBLK 128        // blocks in fused u-kernel (<= #SMs for co-residency)

// ---------------- scratch ----------------
__device__ uint32_t g_bm [Nn * WPR];
__device__ uint32_t g_bmT[Nn * WPR];
__device__ int      g_cols [Nn * SLOTS];
__device__ int      g_colsT[Nn * SLOTS];
__device__ int      g_cnt [Nn];
__device__ int      g_cntT[Nn];
__device__ float    g_dinv[Nn];
__device__ float    g_v[Nn];
__device__ float    g_u[Nn], g_u2[Nn];
__device__ float    g_q[Dd];             // 0.6^4 * 1.5/(u.v) * u^T X   (final scaled)
__device__ float    g_Af[Nn * Dd];       // R fp32 (final-pass base)
__device__ uint2    g_Ab[Nn * D4];       // R bf16 (middle-pass base + iterate0)
__device__ uint2    g_Xb[Nn * D4];       // X bf16 (R-pass + qaccum gathers)
__device__ uint2    g_bf0[Nn * D4];      // iterate ping
__device__ uint2    g_bf1[Nn * D4];      // iterate pong
__device__ int      g_is64;
__device__ int      g_bar[8];            // grid-barrier counters (re-zeroed per call)

// ---------------- helpers ----------------
__device__ __forceinline__ float4 bf2f4(uint2 r) {
    float2 a = __bfloat1622float2(*(__nv_bfloat162*)&r.x);
    float2 b = __bfloat1622float2(*(__nv_bfloat162*)&r.y);
    return make_float4(a.x, a.y, b.x, b.y);
}
__device__ __forceinline__ uint2 f42bf(float4 x) {
    __nv_bfloat162 p0 = __float22bfloat162_rn(make_float2(x.x, x.y));
    __nv_bfloat162 p1 = __float22bfloat162_rn(make_float2(x.z, x.w));
    uint2 o; o.x = *(uint32_t*)&p0; o.y = *(uint32_t*)&p1;
    return o;
}
// software grid barrier (all blocks co-resident)
__device__ __forceinline__ void gridbar(int idx, int nb) {
    __syncthreads();
    if (threadIdx.x == 0) {
        __threadfence();
        atomicAdd(&g_bar[idx], 1);
        volatile int* p = &g_bar[idx];
        while (*p < nb) {}
    }
    __syncthreads();
}

// ---------------- init: zero bitmaps + barriers + q, u=1, sniff dtype ------------
__global__ void k_init(const int* __restrict__ ei32) {
    int gid = blockIdx.x * blockDim.x + threadIdx.x;   // 1024 x 256
    if (gid < Nn * WPR / 4)  ((uint4*)g_bm )[gid]            = make_uint4(0,0,0,0);
    else                     ((uint4*)g_bmT)[gid - Nn*WPR/4] = make_uint4(0,0,0,0);
    if (gid < Nn)  g_u[gid] = 1.0f;
    if (gid < Dd)  g_q[gid] = 0.0f;
    if (gid < 8)   g_bar[gid] = 0;
    if (blockIdx.x == 1023 && threadIdx.x < 32) {
        int t = threadIdx.x, acc = 0;
        for (int k = t; k < 1024; k += 32) acc |= ei32[2*k + 1];
#pragma unroll
        for (int d = 16; d; d >>= 1) acc |= __shfl_xor_sync(0xFFFFFFFFu, acc, d);
        if (t == 0) g_is64 = (acc == 0);
    }
}

__global__ void k_scatter2(const int* __restrict__ ei32) {
    int e = blockIdx.x * blockDim.x + threadIdx.x;
    if (e < NE) {
        int s, d;
        if (g_is64) { s = ei32[2*e]; d = ei32[2*(NE+e)]; }
        else        { s = ei32[e];   d = ei32[NE+e]; }
        atomicOr(&g_bm [s * WPR + (d >> 5)], 1u << (d & 31));
        atomicOr(&g_bmT[d * WPR + (s >> 5)], 1u << (s & 31));
    }
}

// build fwd+transpose CSR (blocks 0..1023) and X->bf16 (blocks 1024..3071)
__global__ void k_build_x2bf(const float4* __restrict__ x) {
    if (blockIdx.x < 1024) {
        int warp = (blockIdx.x * blockDim.x + threadIdx.x) >> 5;
        int lane = threadIdx.x & 31;
        int fwd = (warp < Nn);
        int row = fwd ? warp : warp - Nn;
        const uint32_t* rowbm = fwd ? &g_bm[row * WPR] : &g_bmT[row * WPR];
        int* dst  = fwd ? &g_cols[row * SLOTS] : &g_colsT[row * SLOTS];
        uint32_t w[4]; int c = 0;
#pragma unroll
        for (int k = 0; k < 4; k++) { w[k] = rowbm[lane*4 + k]; c += __popc(w[k]); }
        int incl = c;
#pragma unroll
        for (int d = 1; d < 32; d <<= 1) {
            int t = __shfl_up_sync(0xFFFFFFFFu, incl, d);
            if (lane >= d) incl += t;
        }
        int total = __shfl_sync(0xFFFFFFFFu, incl, 31);
        int off = incl - c;
#pragma unroll
        for (int k = 0; k < 4; k++) {
            uint32_t m = w[k];
            int base = (lane*4 + k) << 5;
            while (m) { int b = __ffs(m) - 1; m &= m - 1; dst[off++] = base + b; }
        }
        if (lane == 0) {
            if (fwd) {
                g_cnt[row] = total;
                float deg = (float)(total + 1);
                g_dinv[row] = rsqrtf(deg);
                g_v[row]    = sqrtf(deg);
            } else {
                g_cntT[row] = total;
            }
        }
    } else {
        int i = (blockIdx.x - 1024) * blockDim.x + threadIdx.x;
        g_Xb[i] = f42bf(x[i]);
    }
}

// ---------------- u-pipeline: 3 power iters + q = 0.6^4*1.5*u^T X/(u.v) ----------
// grid = UPBLK x 1024, co-resident. qaccum reads bf16 X. Per-column atomics: 128.
__global__ __launch_bounds__(1024) void k_upower() {
    int b    = blockIdx.x;
    int t    = threadIdx.x;
    int wid  = t >> 5;          // 32 warps -> 32 rows per block
    int lane = t & 31;
    int rowsPerBlk = Nn / UPBLK;            // 32
    int row = b * rowsPerBlk + wid;

    // 3 power iterations on Ahat^T: u -> u2 -> u -> u2   (final in g_u2)
#pragma unroll
    for (int it = 0; it < 3; it++) {
        const float* src = (it == 1) ? g_u2 : g_u;
        float*       dst = (it == 1) ? g_u  : g_u2;
        int cnt = g_cntT[row];
        const int* cols = &g_colsT[row * SLOTS];
        float s = 0.f;
        for (int k = lane; k < cnt; k += 32)
            s += g_dinv[cols[k]] * src[cols[k]];
#pragma unroll
        for (int d = 16; d; d >>= 1) s += __shfl_down_sync(0xFFFFFFFFu, s, d);
        if (lane == 0) {
            float di = g_dinv[row];
            dst[row] = di * (s + di * src[row]);
        }
        gridbar(it, UPBLK);
    }

    // qaccum over bf16 X: block b covers rows [b*32, b*32+32)
    // thread t: col2 = t&255 (bf16x2 pair), half = t>>8 (0..3 -> 8 rows each)
    {
        __shared__ float sh[Dd];
        int col2 = t & 255;                  // 256 uint32 pairs = 512 cols
        int part = t >> 8;                   // 4 partitions x 8 rows
        int r0 = b * rowsPerBlk + part * 8;
        float s0 = 0.f, s1 = 0.f;
        const uint32_t* xb32 = (const uint32_t*)g_Xb;
        for (int k = 0; k < 8; k++) {
            float ur = g_u2[r0 + k];
            uint32_t p = __ldg(&xb32[(long)(r0 + k) * 256 + col2]);
            float2 f = __bfloat1622float2(*(__nv_bfloat162*)&p);
            s0 += ur * f.x; s1 += ur * f.y;
        }
        if (part == 0) { sh[2*col2] = s0; sh[2*col2+1] = s1; }
        __syncthreads();
        if (part == 1) { sh[2*col2] += s0; sh[2*col2+1] += s1; }
        __syncthreads();
        if (part == 2) { sh[2*col2] += s0; sh[2*col2+1] += s1; }
        __syncthreads();
        if (part == 3) { sh[2*col2] += s0; sh[2*col2+1] += s1; }
        __syncthreads();
        if (t < Dd) atomicAdd(&g_q[t], sh[t]);
    }
    gridbar(3, UPBLK);

    // block 0: scale q by 0.6^4 * 1.5 / (u.v)
    if (b == 0) {
        __shared__ float sh2[32];
        __shared__ float scale;
        float s = 0.f;
        for (int i = t; i < Nn; i += 1024) s += g_u2[i] * g_v[i];
#pragma unroll
        for (int d = 16; d; d >>= 1) s += __shfl_down_sync(0xFFFFFFFFu, s, d);
        if (lane == 0) sh2[wid] = s;
        __syncthreads();
        if (t < 32) {
            s = sh2[t];
#pragma unroll
            for (int d = 16; d; d >>= 1) s += __shfl_down_sync(0xFFFFFFFFu, s, d);
            if (t == 0) scale = 0.1944f / s;    // 0.6^4 * 1.5 / (u.v)
        }
        __syncthreads();
        if (t < Dd) g_q[t] *= scale;
    }
}

// ---------------- R pass: R = (I + 0.5*Ahat)X  (q-free) ----------------
__global__ __launch_bounds__(128) void k_Rpass(
    const float4* __restrict__ xf, const uint2* __restrict__ xb,
    float4* __restrict__ outf, uint2* __restrict__ outb)
{
    int row = blockIdx.x;
    int col = threadIdx.x;
    int cnt = g_cnt[row];
    float di = g_dinv[row];
    const int* cols = &g_cols[row * SLOTS];
    long idx = (long)row * D4 + col;

    float4 xi = __ldg(&xf[idx]);
    float4 s;
    s.x = di * xi.x; s.y = di * xi.y; s.z = di * xi.z; s.w = di * xi.w;

    int k = 0;
    for (; k + 4 <= cnt; k += 4) {
        int j0 = __ldg(&cols[k]),   j1 = __ldg(&cols[k+1]);
        int j2 = __ldg(&cols[k+2]), j3 = __ldg(&cols[k+3]);
        float w0 = __ldg(&g_dinv[j0]), w1 = __ldg(&g_dinv[j1]);
        float w2 = __ldg(&g_dinv[j2]), w3 = __ldg(&g_dinv[j3]);
        float4 v0 = bf2f4(__ldg(&xb[(long)j0 * D4 + col]));
        float4 v1 = bf2f4(__ldg(&xb[(long)j1 * D4 + col]));
        float4 v2 = bf2f4(__ldg(&xb[(long)j2 * D4 + col]));
        float4 v3 = bf2f4(__ldg(&xb[(long)j3 * D4 + col]));
        s.x += w0*v0.x + w1*v1.x + w2*v2.x + w3*v3.x;
        s.y += w0*v0.y + w1*v1.y + w2*v2.y + w3*v3.y;
        s.z += w0*v0.z + w1*v1.z + w2*v2.z + w3*v3.z;
        s.w += w0*v0.w + w1*v1.w + w2*v2.w + w3*v3.w;
    }
    for (; k < cnt; k++) {
        int j = __ldg(&cols[k]);
        float w = __ldg(&g_dinv[j]);
        float4 v = bf2f4(__ldg(&xb[(long)j * D4 + col]));
        s.x += w*v.x; s.y += w*v.y; s.z += w*v.z; s.w += w*v.w;
    }
    float hd = 0.5f * di;
    float4 o;
    o.x = xi.x + hd*s.x;
    o.y = xi.y + hd*s.y;
    o.z = xi.z + hd*s.z;
    o.w = xi.w + hd*s.w;
    outf[idx] = o;
    outb[idx] = f42bf(o);
}

// ---------------- middle bulk pass (all-bf16) ----------------
__global__ __launch_bounds__(128) void k_bulk(
    const uint2* __restrict__ inb, const uint2* __restrict__ baseb,
    uint2* __restrict__ outb)
{
    int row = blockIdx.x;
    int col = threadIdx.x;
    int cnt = g_cnt[row];
    float di = g_dinv[row];
    const int* cols = &g_cols[row * SLOTS];
    long idx = (long)row * D4 + col;

    float4 sv = bf2f4(__ldg(&inb[idx]));
    float4 s;
    s.x = di * sv.x; s.y = di * sv.y; s.z = di * sv.z; s.w = di * sv.w;

    int k = 0;
    for (; k + 4 <= cnt; k += 4) {
        int j0 = __ldg(&cols[k]),   j1 = __ldg(&cols[k+1]);
        int j2 = __ldg(&cols[k+2]), j3 = __ldg(&cols[k+3]);
        float w0 = __ldg(&g_dinv[j0]), w1 = __ldg(&g_dinv[j1]);
        float w2 = __ldg(&g_dinv[j2]), w3 = __ldg(&g_dinv[j3]);
        float4 v0 = bf2f4(__ldg(&inb[(long)j0 * D4 + col]));
        float4 v1 = bf2f4(__ldg(&inb[(long)j1 * D4 + col]));
        float4 v2 = bf2f4(__ldg(&inb[(long)j2 * D4 + col]));
        float4 v3 = bf2f4(__ldg(&inb[(long)j3 * D4 + col]));
        s.x += w0*v0.x + w1*v1.x + w2*v2.x + w3*v3.x;
        s.y += w0*v0.y + w1*v1.y + w2*v2.y + w3*v3.y;
        s.z += w0*v0.z + w1*v1.z + w2*v2.z + w3*v3.z;
        s.w += w0*v0.w + w1*v1.w + w2*v2.w + w3*v3.w;
    }
    for (; k < cnt; k++) {
        int j = __ldg(&cols[k]);
        float w = __ldg(&g_dinv[j]);
        float4 v = bf2f4(__ldg(&inb[(long)j * D4 + col]));
        s.x += w*v.x; s.y += w*v.y; s.z += w*v.z; s.w += w*v.w;
    }
    float4 bs = bf2f4(__ldg(&baseb[idx]));
    float bd = 0.6f * di;
    float4 o;
    o.x = bs.x + bd*s.x; o.y = bs.y + bd*s.y;
    o.z = bs.z + bd*s.z; o.w = bs.w + bd*s.w;
    outb[idx] = f42bf(o);
}

// ---------------- final: Y = 0.4*R + 0.24*Ahat*acc + v_i*q (q pre-scaled) --------
__global__ __launch_bounds__(128) void k_final(
    const uint2* __restrict__ inb, const float4* __restrict__ basef,
    float4* __restrict__ out)
{
    int row = blockIdx.x;
    int col = threadIdx.x;
    int cnt = g_cnt[row];
    float di = g_dinv[row];
    const int* cols = &g_cols[row * SLOTS];
    long idx = (long)row * D4 + col;

    float4 sv = bf2f4(__ldg(&inb[idx]));
    float4 s;
    s.x = di * sv.x; s.y = di * sv.y; s.z = di * sv.z; s.w = di * sv.w;

    int k = 0;
    for (; k + 4 <= cnt; k += 4) {
        int j0 = __ldg(&cols[k]),   j1 = __ldg(&cols[k+1]);
        int j2 = __ldg(&cols[k+2]), j3 = __ldg(&cols[k+3]);
        float w0 = __ldg(&g_dinv[j0]), w1 = __ldg(&g_dinv[j1]);
        float w2 = __ldg(&g_dinv[j2]), w3 = __ldg(&g_dinv[j3]);
        float4 v0 = bf2f4(__ldg(&inb[(long)j0 * D4 + col]));
        float4 v1 = bf2f4(__ldg(&inb[(long)j1 * D4 + col]));
        float4 v2 = bf2f4(__ldg(&inb[(long)j2 * D4 + col]));
        float4 v3 = bf2f4(__ldg(&inb[(long)j3 * D4 + col]));
        s.x += w0*v0.x + w1*v1.x + w2*v2.x + w3*v3.x;
        s.y += w0*v0.y + w1*v1.y + w2*v2.y + w3*v3.y;
        s.z += w0*v0.z + w1*v1.z + w2*v2.z + w3*v3.z;
        s.w += w0*v0.w + w1*v1.w + w2*v2.w + w3*v3.w;
    }
    for (; k < cnt; k++) {
        int j = __ldg(&cols[k]);
        float w = __ldg(&g_dinv[j]);
        float4 v = bf2f4(__ldg(&inb[(long)j * D4 + col]));
        s.x += w*v.x; s.y += w*v.y; s.z += w*v.z; s.w += w*v.w;
    }
    float4 bs = __ldg(&basef[idx]);
    float bd = 0.24f * di;
    float rv = g_v[row];
    float4 q = ((const float4*)g_q)[col];
    float4 o;
    o.x = 0.4f*bs.x + bd*s.x + rv*q.x;
    o.y = 0.4f*bs.y + bd*s.y + rv*q.y;
    o.z = 0.4f*bs.z + bd*s.z + rv*q.z;
    o.w = 0.4f*bs.w + bd*s.w + rv*q.w;
    out[idx] = o;
}

// ---------------- launch ----------------
extern "C" void kernel_launch(void* const* d_in, const int* in_sizes, int n_in,
                              void* d_out, int out_size) {
    const float* x    = (const float*)d_in[0];
    const void*  eraw = d_in[1];
    if (in_sizes[0] != Nn * Dd) { x = (const float*)d_in[1]; eraw = d_in[0]; }
    const int* ei32 = (const int*)eraw;
    float4*    yo   = (float4*)d_out;

    float *pAf;  cudaGetSymbolAddress((void**)&pAf, g_Af);
    uint2 *pAb;  cudaGetSymbolAddress((void**)&pAb, g_Ab);
    uint2 *pXb;  cudaGetSymbolAddress((void**)&pXb, g_Xb);
    uint2 *pbf0; cudaGetSymbolAddress((void**)&pbf0, g_bf0);
    uint2 *pbf1; cudaGetSymbolAddress((void**)&pbf1, g_bf1);

    // 1) zero bitmaps/barriers/q, u=1, dtype sniff
    k_init<<<1024, 256>>>(ei32);
    // 2) edge scatter into dedupe bitmaps (fwd + transpose)
    k_scatter2<<<NE / 256, 256>>>(ei32);
    // 3) CSR build (fwd+T) + X->bf16
    k_build_x2bf<<<3072, 256>>>((const float4*)x);
    // 4) 3 power iterations + q (bf16-X accumulation, 128 atomics/col) + scale
    k_upower<<<UPBLK, 1024>>>();
    // 5) R = (I + 0.5*Ahat)X  (fp32 + bf16)
    k_Rpass<<<Nn, 128>>>((const float4*)x, pXb, (float4*)pAf, pAb);
    // 6-7) two middle bulk passes (bf16): acc <- R + 0.6*Ahat*acc
    k_bulk<<<Nn, 128>>>(pAb,  pAb, pbf0);
    k_bulk<<<Nn, 128>>>(pbf0, pAb, pbf1);
    // 8) final: Y = 0.4*(R + 0.6*Ahat*acc) + 0.6^4*v*q_R
    k_final<<<Nn, 128>>>(pbf1, (const float4*)pAf, yo);
}

// round 10
// speedup vs baseline: 2.6820x; 1.1568x over previous
#include <cuda_runtime.h>
#include <cuda_bf16.h>
#include <stdint.h>

#define Nn    4096
#define Dd    512
#define D4    128        // Dd/4
#define NE    131072
#define WPR   128
#define SLOTS 128

// ---------------- scratch ----------------
__device__ uint32_t g_bm [Nn * WPR];
__device__ uint32_t g_bmT[Nn * WPR];
__device__ int      g_cols [Nn * SLOTS];
__device__ int      g_colsT[Nn * SLOTS];
__device__ int      g_cnt [Nn];
__device__ int      g_cntT[Nn];
__device__ float    g_dinv[Nn];
__device__ float    g_v[Nn];
__device__ float    g_u[Nn], g_u2[Nn];
__device__ float    g_q[Dd];             // 0.6^4*1.5/(u.v) * u^T X (after qscale)
__device__ float    g_Af[Nn * Dd];       // R fp32 (final-pass base)
__device__ uint2    g_Ab[Nn * D4];       // R bf16 (middle-pass base + iterate0)
__device__ uint2    g_Xb[Nn * D4];       // X bf16 (R-pass + qaccum gathers)
__device__ uint2    g_bf0[Nn * D4];      // iterate ping
__device__ uint2    g_bf1[Nn * D4];      // iterate pong
__device__ int      g_is64;

// ---------------- helpers ----------------
__device__ __forceinline__ float4 bf2f4(uint2 r) {
    float2 a = __bfloat1622float2(*(__nv_bfloat162*)&r.x);
    float2 b = __bfloat1622float2(*(__nv_bfloat162*)&r.y);
    return make_float4(a.x, a.y, b.x, b.y);
}
__device__ __forceinline__ uint2 f42bf(float4 x) {
    __nv_bfloat162 p0 = __float22bfloat162_rn(make_float2(x.x, x.y));
    __nv_bfloat162 p1 = __float22bfloat162_rn(make_float2(x.z, x.w));
    uint2 o; o.x = *(uint32_t*)&p0; o.y = *(uint32_t*)&p1;
    return o;
}

// ---------------- init: zero bitmaps + q, u=1, sniff dtype ----------------
__global__ void k_init(const int* __restrict__ ei32) {
    int gid = blockIdx.x * blockDim.x + threadIdx.x;   // 1024 x 256
    if (gid < Nn * WPR / 4)  ((uint4*)g_bm )[gid]            = make_uint4(0,0,0,0);
    else                     ((uint4*)g_bmT)[gid - Nn*WPR/4] = make_uint4(0,0,0,0);
    if (gid < Nn)  g_u[gid] = 1.0f;
    if (gid < Dd)  g_q[gid] = 0.0f;
    if (blockIdx.x == 1023 && threadIdx.x < 32) {
        int t = threadIdx.x, acc = 0;
        for (int k = t; k < 1024; k += 32) acc |= ei32[2*k + 1];
#pragma unroll
        for (int d = 16; d; d >>= 1) acc |= __shfl_xor_sync(0xFFFFFFFFu, acc, d);
        if (t == 0) g_is64 = (acc == 0);
    }
}

__global__ void k_scatter2(const int* __restrict__ ei32) {
    int e = blockIdx.x * blockDim.x + threadIdx.x;
    if (e < NE) {
        int s, d;
        if (g_is64) { s = ei32[2*e]; d = ei32[2*(NE+e)]; }
        else        { s = ei32[e];   d = ei32[NE+e]; }
        atomicOr(&g_bm [s * WPR + (d >> 5)], 1u << (d & 31));
        atomicOr(&g_bmT[d * WPR + (s >> 5)], 1u << (s & 31));
    }
}

// build fwd+transpose CSR (blocks 0..1023) and X->bf16 (blocks 1024..3071)
__global__ void k_build_x2bf(const float4* __restrict__ x) {
    if (blockIdx.x < 1024) {
        int warp = (blockIdx.x * blockDim.x + threadIdx.x) >> 5;
        int lane = threadIdx.x & 31;
        int fwd = (warp < Nn);
        int row = fwd ? warp : warp - Nn;
        const uint32_t* rowbm = fwd ? &g_bm[row * WPR] : &g_bmT[row * WPR];
        int* dst  = fwd ? &g_cols[row * SLOTS] : &g_colsT[row * SLOTS];
        uint32_t w[4]; int c = 0;
#pragma unroll
        for (int k = 0; k < 4; k++) { w[k] = rowbm[lane*4 + k]; c += __popc(w[k]); }
        int incl = c;
#pragma unroll
        for (int d = 1; d < 32; d <<= 1) {
            int t = __shfl_up_sync(0xFFFFFFFFu, incl, d);
            if (lane >= d) incl += t;
        }
        int total = __shfl_sync(0xFFFFFFFFu, incl, 31);
        int off = incl - c;
#pragma unroll
        for (int k = 0; k < 4; k++) {
            uint32_t m = w[k];
            int base = (lane*4 + k) << 5;
            while (m) { int b = __ffs(m) - 1; m &= m - 1; dst[off++] = base + b; }
        }
        if (lane == 0) {
            if (fwd) {
                g_cnt[row] = total;
                float deg = (float)(total + 1);
                g_dinv[row] = rsqrtf(deg);
                g_v[row]    = sqrtf(deg);
            } else {
                g_cntT[row] = total;
            }
        }
    } else {
        int i = (blockIdx.x - 1024) * blockDim.x + threadIdx.x;
        g_Xb[i] = f42bf(x[i]);
    }
}

// ---------------- side-stream: one power iteration (Ahat^T) ----------------
__global__ __launch_bounds__(1024) void k_pow(const float* __restrict__ src,
                                              float* __restrict__ dst) {
    int row  = blockIdx.x * 32 + (threadIdx.x >> 5);   // 128 blocks x 32 warps
    int lane = threadIdx.x & 31;
    int cnt = g_cntT[row];
    const int* cols = &g_colsT[row * SLOTS];
    float s = 0.f;
    for (int k = lane; k < cnt; k += 32)
        s += g_dinv[cols[k]] * src[cols[k]];
#pragma unroll
    for (int d = 16; d; d >>= 1) s += __shfl_down_sync(0xFFFFFFFFu, s, d);
    if (lane == 0) {
        float di = g_dinv[row];
        dst[row] = di * (s + di * src[row]);
    }
}

// ---------------- side-stream: q partial sums (bf16 X), 128 atomics/col ---------
__global__ __launch_bounds__(1024) void k_qaccum() {
    __shared__ float sh[Dd];
    int t = threadIdx.x;
    int col2 = t & 255;                  // 256 bf16x2 pairs = 512 cols
    int part = t >> 8;                   // 4 partitions x 8 rows
    int r0 = blockIdx.x * 32 + part * 8;
    float s0 = 0.f, s1 = 0.f;
    const uint32_t* xb32 = (const uint32_t*)g_Xb;
    for (int k = 0; k < 8; k++) {
        float ur = g_u2[r0 + k];
        uint32_t p = __ldg(&xb32[(long)(r0 + k) * 256 + col2]);
        float2 f = __bfloat1622float2(*(__nv_bfloat162*)&p);
        s0 += ur * f.x; s1 += ur * f.y;
    }
    if (part == 0) { sh[2*col2] = s0; sh[2*col2+1] = s1; }
    __syncthreads();
    if (part == 1) { sh[2*col2] += s0; sh[2*col2+1] += s1; }
    __syncthreads();
    if (part == 2) { sh[2*col2] += s0; sh[2*col2+1] += s1; }
    __syncthreads();
    if (part == 3) { sh[2*col2] += s0; sh[2*col2+1] += s1; }
    __syncthreads();
    if (t < Dd) atomicAdd(&g_q[t], sh[t]);
}

// ---------------- side-stream: scale q by 0.6^4 * 1.5 / (u.v) ----------------
__global__ __launch_bounds__(1024) void k_qscale() {
    __shared__ float sh[32];
    __shared__ float scale;
    int t = threadIdx.x, lane = t & 31, wid = t >> 5;
    float s = 0.f;
    for (int i = t; i < Nn; i += 1024) s += g_u2[i] * g_v[i];
#pragma unroll
    for (int d = 16; d; d >>= 1) s += __shfl_down_sync(0xFFFFFFFFu, s, d);
    if (lane == 0) sh[wid] = s;
    __syncthreads();
    if (t < 32) {
        s = sh[t];
#pragma unroll
        for (int d = 16; d; d >>= 1) s += __shfl_down_sync(0xFFFFFFFFu, s, d);
        if (t == 0) scale = 0.1944f / s;    // 0.6^4 * 1.5 / (u.v)
    }
    __syncthreads();
    if (t < Dd) g_q[t] *= scale;
}

// ---------------- R pass: R = (I + 0.5*Ahat)X ----------------
__global__ __launch_bounds__(128) void k_Rpass(
    const float4* __restrict__ xf, const uint2* __restrict__ xb,
    float4* __restrict__ outf, uint2* __restrict__ outb)
{
    int row = blockIdx.x;
    int col = threadIdx.x;
    int cnt = g_cnt[row];
    float di = g_dinv[row];
    const int* cols = &g_cols[row * SLOTS];
    long idx = (long)row * D4 + col;

    float4 xi = __ldg(&xf[idx]);
    float4 s;
    s.x = di * xi.x; s.y = di * xi.y; s.z = di * xi.z; s.w = di * xi.w;

    int k = 0;
    for (; k + 4 <= cnt; k += 4) {
        int j0 = __ldg(&cols[k]),   j1 = __ldg(&cols[k+1]);
        int j2 = __ldg(&cols[k+2]), j3 = __ldg(&cols[k+3]);
        float w0 = __ldg(&g_dinv[j0]), w1 = __ldg(&g_dinv[j1]);
        float w2 = __ldg(&g_dinv[j2]), w3 = __ldg(&g_dinv[j3]);
        float4 v0 = bf2f4(__ldg(&xb[(long)j0 * D4 + col]));
        float4 v1 = bf2f4(__ldg(&xb[(long)j1 * D4 + col]));
        float4 v2 = bf2f4(__ldg(&xb[(long)j2 * D4 + col]));
        float4 v3 = bf2f4(__ldg(&xb[(long)j3 * D4 + col]));
        s.x += w0*v0.x + w1*v1.x + w2*v2.x + w3*v3.x;
        s.y += w0*v0.y + w1*v1.y + w2*v2.y + w3*v3.y;
        s.z += w0*v0.z + w1*v1.z + w2*v2.z + w3*v3.z;
        s.w += w0*v0.w + w1*v1.w + w2*v2.w + w3*v3.w;
    }
    for (; k < cnt; k++) {
        int j = __ldg(&cols[k]);
        float w = __ldg(&g_dinv[j]);
        float4 v = bf2f4(__ldg(&xb[(long)j * D4 + col]));
        s.x += w*v.x; s.y += w*v.y; s.z += w*v.z; s.w += w*v.w;
    }
    float hd = 0.5f * di;
    float4 o;
    o.x = xi.x + hd*s.x;
    o.y = xi.y + hd*s.y;
    o.z = xi.z + hd*s.z;
    o.w = xi.w + hd*s.w;
    outf[idx] = o;
    outb[idx] = f42bf(o);
}

// ---------------- middle bulk pass (all-bf16) ----------------
__global__ __launch_bounds__(128) void k_bulk(
    const uint2* __restrict__ inb, const uint2* __restrict__ baseb,
    uint2* __restrict__ outb)
{
    int row = blockIdx.x;
    int col = threadIdx.x;
    int cnt = g_cnt[row];
    float di = g_dinv[row];
    const int* cols = &g_cols[row * SLOTS];
    long idx = (long)row * D4 + col;

    float4 sv = bf2f4(__ldg(&inb[idx]));
    float4 s;
    s.x = di * sv.x; s.y = di * sv.y; s.z = di * sv.z; s.w = di * sv.w;

    int k = 0;
    for (; k + 4 <= cnt; k += 4) {
        int j0 = __ldg(&cols[k]),   j1 = __ldg(&cols[k+1]);
        int j2 = __ldg(&cols[k+2]), j3 = __ldg(&cols[k+3]);
        float w0 = __ldg(&g_dinv[j0]), w1 = __ldg(&g_dinv[j1]);
        float w2 = __ldg(&g_dinv[j2]), w3 = __ldg(&g_dinv[j3]);
        float4 v0 = bf2f4(__ldg(&inb[(long)j0 * D4 + col]));
        float4 v1 = bf2f4(__ldg(&inb[(long)j1 * D4 + col]));
        float4 v2 = bf2f4(__ldg(&inb[(long)j2 * D4 + col]));
        float4 v3 = bf2f4(__ldg(&inb[(long)j3 * D4 + col]));
        s.x += w0*v0.x + w1*v1.x + w2*v2.x + w3*v3.x;
        s.y += w0*v0.y + w1*v1.y + w2*v2.y + w3*v3.y;
        s.z += w0*v0.z + w1*v1.z + w2*v2.z + w3*v3.z;
        s.w += w0*v0.w + w1*v1.w + w2*v2.w + w3*v3.w;
    }
    for (; k < cnt; k++) {
        int j = __ldg(&cols[k]);
        float w = __ldg(&g_dinv[j]);
        float4 v = bf2f4(__ldg(&inb[(long)j * D4 + col]));
        s.x += w*v.x; s.y += w*v.y; s.z += w*v.z; s.w += w*v.w;
    }
    float4 bs = bf2f4(__ldg(&baseb[idx]));
    float bd = 0.6f * di;
    float4 o;
    o.x = bs.x + bd*s.x; o.y = bs.y + bd*s.y;
    o.z = bs.z + bd*s.z; o.w = bs.w + bd*s.w;
    outb[idx] = f42bf(o);
}

// ---------------- final: Y = 0.4*R + 0.24*Ahat*acc + v_i*q ----------------
__global__ __launch_bounds__(128) void k_final(
    const uint2* __restrict__ inb, const float4* __restrict__ basef,
    float4* __restrict__ out)
{
    int row = blockIdx.x;
    int col = threadIdx.x;
    int cnt = g_cnt[row];
    float di = g_dinv[row];
    const int* cols = &g_cols[row * SLOTS];
    long idx = (long)row * D4 + col;

    float4 sv = bf2f4(__ldg(&inb[idx]));
    float4 s;
    s.x = di * sv.x; s.y = di * sv.y; s.z = di * sv.z; s.w = di * sv.w;

    int k = 0;
    for (; k + 4 <= cnt; k += 4) {
        int j0 = __ldg(&cols[k]),   j1 = __ldg(&cols[k+1]);
        int j2 = __ldg(&cols[k+2]), j3 = __ldg(&cols[k+3]);
        float w0 = __ldg(&g_dinv[j0]), w1 = __ldg(&g_dinv[j1]);
        float w2 = __ldg(&g_dinv[j2]), w3 = __ldg(&g_dinv[j3]);
        float4 v0 = bf2f4(__ldg(&inb[(long)j0 * D4 + col]));
        float4 v1 = bf2f4(__ldg(&inb[(long)j1 * D4 + col]));
        float4 v2 = bf2f4(__ldg(&inb[(long)j2 * D4 + col]));
        float4 v3 = bf2f4(__ldg(&inb[(long)j3 * D4 + col]));
        s.x += w0*v0.x + w1*v1.x + w2*v2.x + w3*v3.x;
        s.y += w0*v0.y + w1*v1.y + w2*v2.y + w3*v3.y;
        s.z += w0*v0.z + w1*v1.z + w2*v2.z + w3*v3.z;
        s.w += w0*v0.w + w1*v1.w + w2*v2.w + w3*v3.w;
    }
    for (; k < cnt; k++) {
        int j = __ldg(&cols[k]);
        float w = __ldg(&g_dinv[j]);
        float4 v = bf2f4(__ldg(&inb[(long)j * D4 + col]));
        s.x += w*v.x; s.y += w*v.y; s.z += w*v.z; s.w += w*v.w;
    }
    float4 bs = __ldg(&basef[idx]);
    float bd = 0.24f * di;
    float rv = g_v[row];
    float4 q = ((const float4*)g_q)[col];
    float4 o;
    o.x = 0.4f*bs.x + bd*s.x + rv*q.x;
    o.y = 0.4f*bs.y + bd*s.y + rv*q.y;
    o.z = 0.4f*bs.z + bd*s.z + rv*q.z;
    o.w = 0.4f*bs.w + bd*s.w + rv*q.w;
    out[idx] = o;
}

// ---------------- launch ----------------
extern "C" void kernel_launch(void* const* d_in, const int* in_sizes, int n_in,
                              void* d_out, int out_size) {
    const float* x    = (const float*)d_in[0];
    const void*  eraw = d_in[1];
    if (in_sizes[0] != Nn * Dd) { x = (const float*)d_in[1]; eraw = d_in[0]; }
    const int* ei32 = (const int*)eraw;
    float4*    yo   = (float4*)d_out;

    float *pAf;  cudaGetSymbolAddress((void**)&pAf, g_Af);
    uint2 *pAb;  cudaGetSymbolAddress((void**)&pAb, g_Ab);
    uint2 *pXb;  cudaGetSymbolAddress((void**)&pXb, g_Xb);
    uint2 *pbf0; cudaGetSymbolAddress((void**)&pbf0, g_bf0);
    uint2 *pbf1; cudaGetSymbolAddress((void**)&pbf1, g_bf1);
    float *pu;   cudaGetSymbolAddress((void**)&pu,  g_u);
    float *pu2;  cudaGetSymbolAddress((void**)&pu2, g_u2);

    // side stream + fork/join events (host-side resources; created per call,
    // only ever executed during the capture/correctness calls, not replays)
    cudaStream_t s2;
    cudaStreamCreateWithFlags(&s2, cudaStreamNonBlocking);
    cudaEvent_t evF, evJ;
    cudaEventCreateWithFlags(&evF, cudaEventDisableTiming);
    cudaEventCreateWithFlags(&evJ, cudaEventDisableTiming);

    // ---- main stream: structure ----
    k_init<<<1024, 256>>>(ei32);
    k_scatter2<<<NE / 256, 256>>>(ei32);
    k_build_x2bf<<<3072, 256>>>((const float4*)x);

    // ---- fork: u/q pipeline on side stream (only k_final consumes it) ----
    cudaEventRecord(evF, 0);
    cudaStreamWaitEvent(s2, evF, 0);
    k_pow<<<128, 1024, 0, s2>>>(pu,  pu2);
    k_pow<<<128, 1024, 0, s2>>>(pu2, pu);
    k_pow<<<128, 1024, 0, s2>>>(pu,  pu2);   // final u in g_u2
    k_qaccum<<<128, 1024, 0, s2>>>();
    k_qscale<<<1, 1024, 0, s2>>>();
    cudaEventRecord(evJ, s2);

    // ---- main stream: heavy passes (q-independent) ----
    k_Rpass<<<Nn, 128>>>((const float4*)x, pXb, (float4*)pAf, pAb);
    k_bulk<<<Nn, 128>>>(pAb,  pAb, pbf0);
    k_bulk<<<Nn, 128>>>(pbf0, pAb, pbf1);

    // ---- join, then final ----
    cudaStreamWaitEvent(0, evJ, 0);
    k_final<<<Nn, 128>>>(pbf1, (const float4*)pAf, yo);
}